// round 2
// baseline (speedup 1.0000x reference)
#include <cuda_runtime.h>
#include <cuda_bf16.h>
#include <cstdint>

// Problem dims (fixed by the dataset)
#define DD 2048   // hidden size
#define HH 1408   // moe intermediate
#define EE 8      // experts
#define TT 4096   // tokens (B*S)
#define CAP 4096  // per-expert token capacity (worst case)

// ---- routing / scratch state (no allocations allowed -> __device__ globals) ----
__device__ int   g_count[EE];
__device__ int   g_tokens[EE * CAP];
__device__ float g_w[EE * CAP];
__device__ int   g_tidx[TT * 2];
__device__ float g_tw[TT * 2];
// SwiGLU activations, compacted per expert, fp32: 8*4096*1408*4B = 184.5 MB
__device__ float g_G[(size_t)EE * CAP * HH];

// ---------------------------------------------------------------------------
__global__ void k_init() {
    int i = blockIdx.x * blockDim.x + threadIdx.x;
    if (i < EE * CAP) { g_tokens[i] = 0; g_w[i] = 0.0f; }
    if (i < EE) g_count[i] = 0;
}

// ---------------------------------------------------------------------------
// gating: one warp per token; also writes out = x (residual init).
// ---------------------------------------------------------------------------
__global__ void k_gate(const float* __restrict__ x,
                       const float* __restrict__ Wg,
                       float* __restrict__ out) {
    int warp = threadIdx.x >> 5, lane = threadIdx.x & 31;
    int t = blockIdx.x * 8 + warp;
    float a[EE];
#pragma unroll
    for (int e = 0; e < EE; e++) a[e] = 0.0f;
    const float* xr = x + (size_t)t * DD;
    float* orow = out + (size_t)t * DD;
    for (int k = lane; k < DD; k += 32) {
        float xv = xr[k];
        orow[k] = xv;
#pragma unroll
        for (int e = 0; e < EE; e++) a[e] += xv * Wg[e * DD + k];
    }
#pragma unroll
    for (int off = 16; off; off >>= 1) {
#pragma unroll
        for (int e = 0; e < EE; e++) a[e] += __shfl_xor_sync(0xffffffffu, a[e], off);
    }
    if (lane == 0) {
        float m = a[0];
#pragma unroll
        for (int e = 1; e < EE; e++) m = fmaxf(m, a[e]);
        float s = 0.0f;
#pragma unroll
        for (int e = 0; e < EE; e++) s += expf(a[e] - m);
        // top-2, jax tie semantics (first index wins)
        int i1 = 0;
#pragma unroll
        for (int e = 1; e < EE; e++) if (a[e] > a[i1]) i1 = e;
        int i2 = (i1 == 0) ? 1 : 0;
#pragma unroll
        for (int e = 0; e < EE; e++) if (e != i1 && a[e] > a[i2]) i2 = e;
        float w1 = expf(a[i1] - m) / s;
        float w2 = expf(a[i2] - m) / s;
        g_tidx[t * 2 + 0] = i1; g_tw[t * 2 + 0] = w1;
        g_tidx[t * 2 + 1] = i2; g_tw[t * 2 + 1] = w2;
    }
}

// ---------------------------------------------------------------------------
__global__ void k_route() {
    int t = blockIdx.x * blockDim.x + threadIdx.x;
    if (t >= TT) return;
#pragma unroll
    for (int k = 0; k < 2; k++) {
        int e = g_tidx[t * 2 + k];
        int pos = atomicAdd(&g_count[e], 1);
        g_tokens[e * CAP + pos] = t;
        g_w[e * CAP + pos] = g_tw[t * 2 + k];
    }
}

// ---------------------------------------------------------------------------
// warp-level tf32 mma m16n8k8, fp32 accumulate
// ---------------------------------------------------------------------------
__device__ __forceinline__ void mma_tf32(float* c, const uint32_t* a,
                                         uint32_t b0, uint32_t b1) {
    asm volatile(
        "mma.sync.aligned.m16n8k8.row.col.f32.tf32.tf32.f32 "
        "{%0,%1,%2,%3},{%4,%5,%6,%7},{%8,%9},{%0,%1,%2,%3};"
        : "+f"(c[0]), "+f"(c[1]), "+f"(c[2]), "+f"(c[3])
        : "r"(a[0]), "r"(a[1]), "r"(a[2]), "r"(a[3]), "r"(b0), "r"(b1));
}

__device__ __forceinline__ uint32_t f2tf(float v) {
    uint32_t r;
    asm("cvt.rna.tf32.f32 %0, %1;" : "=r"(r) : "f"(v));
    return r;
}

__device__ __forceinline__ uint4 f4totf(float4 v) {
    uint4 u;
    u.x = f2tf(v.x); u.y = f2tf(v.y); u.z = f2tf(v.z); u.w = f2tf(v.w);
    return u;
}

__device__ __forceinline__ float silu_f(float v) { return v / (1.0f + expf(-v)); }

// SMEM row stride 36 words: fragment LDS bank = (4*gr + tg) mod 32 -> conflict-free
#define SPAD 36

// ---------------------------------------------------------------------------
// gemm1: per expert e, gathered rows X_e [cnt, D]; computes
//   G = silu(X_e @ W1_e^T) * (X_e @ W3_e^T)  -> g_G (fp32), tile 64x64, BK=32.
// ---------------------------------------------------------------------------
__global__ void __launch_bounds__(128) k_gemm1(const float* __restrict__ x,
                                               const float* __restrict__ W1,
                                               const float* __restrict__ W3) {
    int e = blockIdx.z;
    int cnt = g_count[e];
    int m0 = blockIdx.x * 64;
    if (m0 >= cnt) return;
    int n0 = blockIdx.y * 64;

    __shared__ __align__(16) uint32_t sA[64][SPAD];
    __shared__ __align__(16) uint32_t sB1[64][SPAD];
    __shared__ __align__(16) uint32_t sB3[64][SPAD];
    __shared__ int srow[64];

    int tid = threadIdx.x;
    if (tid < 64) srow[tid] = g_tokens[e * CAP + m0 + tid];
    __syncthreads();

    int r = tid >> 1, half = tid & 1;
    const float* abase  = x  + (size_t)srow[r] * DD + half * 16;
    const float* w1base = W1 + ((size_t)e * HH + n0 + r) * DD + half * 16;
    const float* w3base = W3 + ((size_t)e * HH + n0 + r) * DD + half * 16;

    int warp = tid >> 5, lane = tid & 31;
    int wm = warp >> 1, wn = warp & 1, gr = lane >> 2, tg = lane & 3;

    float acc1[2][4][4], acc3[2][4][4];
#pragma unroll
    for (int mi = 0; mi < 2; mi++)
#pragma unroll
        for (int ni = 0; ni < 4; ni++)
#pragma unroll
            for (int q = 0; q < 4; q++) { acc1[mi][ni][q] = 0.f; acc3[mi][ni][q] = 0.f; }

    for (int kt = 0; kt < DD / 32; kt++) {
        int k0 = kt * 32;
        const float4* pa = (const float4*)(abase + k0);
        const float4* p1 = (const float4*)(w1base + k0);
        const float4* p3 = (const float4*)(w3base + k0);
#pragma unroll
        for (int j = 0; j < 4; j++) {
            *(uint4*)&sA[r][half * 16 + j * 4]  = f4totf(pa[j]);
            *(uint4*)&sB1[r][half * 16 + j * 4] = f4totf(p1[j]);
            *(uint4*)&sB3[r][half * 16 + j * 4] = f4totf(p3[j]);
        }
        __syncthreads();
#pragma unroll
        for (int ks = 0; ks < 32; ks += 8) {
            uint32_t afr[2][4];
#pragma unroll
            for (int mi = 0; mi < 2; mi++) {
                int rr = wm * 32 + mi * 16 + gr;
                afr[mi][0] = sA[rr][ks + tg];
                afr[mi][1] = sA[rr + 8][ks + tg];
                afr[mi][2] = sA[rr][ks + tg + 4];
                afr[mi][3] = sA[rr + 8][ks + tg + 4];
            }
#pragma unroll
            for (int ni = 0; ni < 4; ni++) {
                int cc = wn * 32 + ni * 8 + gr;
                uint32_t b10 = sB1[cc][ks + tg];
                uint32_t b11 = sB1[cc][ks + tg + 4];
                uint32_t b30 = sB3[cc][ks + tg];
                uint32_t b31 = sB3[cc][ks + tg + 4];
#pragma unroll
                for (int mi = 0; mi < 2; mi++) {
                    mma_tf32(acc1[mi][ni], afr[mi], b10, b11);
                    mma_tf32(acc3[mi][ni], afr[mi], b30, b31);
                }
            }
        }
        __syncthreads();
    }

    // epilogue: G = silu(acc1) * acc3, store fp32 compacted
#pragma unroll
    for (int mi = 0; mi < 2; mi++) {
        int rbase = m0 + wm * 32 + mi * 16 + gr;
        float* gp0 = g_G + ((size_t)e * CAP + rbase) * HH + n0;
        float* gp1 = gp0 + (size_t)8 * HH;
#pragma unroll
        for (int ni = 0; ni < 4; ni++) {
            int cc = wn * 32 + ni * 8 + tg * 2;
            float2 v01, v23;
            v01.x = silu_f(acc1[mi][ni][0]) * acc3[mi][ni][0];
            v01.y = silu_f(acc1[mi][ni][1]) * acc3[mi][ni][1];
            v23.x = silu_f(acc1[mi][ni][2]) * acc3[mi][ni][2];
            v23.y = silu_f(acc1[mi][ni][3]) * acc3[mi][ni][3];
            *(float2*)(gp0 + cc) = v01;
            *(float2*)(gp1 + cc) = v23;
        }
    }
}

// ---------------------------------------------------------------------------
// gemm2: Y_e = G_e @ W2_e^T  [cnt, D], scatter: out[token] += w * row
// ---------------------------------------------------------------------------
__global__ void __launch_bounds__(128) k_gemm2(const float* __restrict__ W2,
                                               float* __restrict__ out) {
    int e = blockIdx.z;
    int cnt = g_count[e];
    int m0 = blockIdx.x * 64;
    if (m0 >= cnt) return;
    int n0 = blockIdx.y * 64;  // output d columns

    __shared__ __align__(16) uint32_t sA[64][SPAD];
    __shared__ __align__(16) uint32_t sB[64][SPAD];

    int tid = threadIdx.x;
    int r = tid >> 1, half = tid & 1;
    const float* abase = g_G + ((size_t)e * CAP + m0 + r) * HH + half * 16;
    const float* bbase = W2 + ((size_t)e * DD + n0 + r) * HH + half * 16;

    int warp = tid >> 5, lane = tid & 31;
    int wm = warp >> 1, wn = warp & 1, gr = lane >> 2, tg = lane & 3;

    float acc[2][4][4];
#pragma unroll
    for (int mi = 0; mi < 2; mi++)
#pragma unroll
        for (int ni = 0; ni < 4; ni++)
#pragma unroll
            for (int q = 0; q < 4; q++) acc[mi][ni][q] = 0.f;

    for (int kt = 0; kt < HH / 32; kt++) {
        int k0 = kt * 32;
        const float4* pa = (const float4*)(abase + k0);
        const float4* pb = (const float4*)(bbase + k0);
#pragma unroll
        for (int j = 0; j < 4; j++) {
            *(uint4*)&sA[r][half * 16 + j * 4] = f4totf(pa[j]);
            *(uint4*)&sB[r][half * 16 + j * 4] = f4totf(pb[j]);
        }
        __syncthreads();
#pragma unroll
        for (int ks = 0; ks < 32; ks += 8) {
            uint32_t afr[2][4];
#pragma unroll
            for (int mi = 0; mi < 2; mi++) {
                int rr = wm * 32 + mi * 16 + gr;
                afr[mi][0] = sA[rr][ks + tg];
                afr[mi][1] = sA[rr + 8][ks + tg];
                afr[mi][2] = sA[rr][ks + tg + 4];
                afr[mi][3] = sA[rr + 8][ks + tg + 4];
            }
#pragma unroll
            for (int ni = 0; ni < 4; ni++) {
                int cc = wn * 32 + ni * 8 + gr;
                uint32_t b0 = sB[cc][ks + tg];
                uint32_t b1 = sB[cc][ks + tg + 4];
#pragma unroll
                for (int mi = 0; mi < 2; mi++)
                    mma_tf32(acc[mi][ni], afr[mi], b0, b1);
            }
        }
        __syncthreads();
    }

    // epilogue: weighted scatter-add into out (out pre-initialized to x)
#pragma unroll
    for (int mi = 0; mi < 2; mi++) {
        int rl = m0 + wm * 32 + mi * 16 + gr;
        int tok0 = g_tokens[e * CAP + rl];
        float w0  = g_w[e * CAP + rl];
        int tok1 = g_tokens[e * CAP + rl + 8];
        float w1  = g_w[e * CAP + rl + 8];
        float* o0 = out + (size_t)tok0 * DD;
        float* o1 = out + (size_t)tok1 * DD;
#pragma unroll
        for (int ni = 0; ni < 4; ni++) {
            int cc = n0 + wn * 32 + ni * 8 + tg * 2;
            atomicAdd(o0 + cc,     w0 * acc[mi][ni][0]);
            atomicAdd(o0 + cc + 1, w0 * acc[mi][ni][1]);
            atomicAdd(o1 + cc,     w1 * acc[mi][ni][2]);
            atomicAdd(o1 + cc + 1, w1 * acc[mi][ni][3]);
        }
    }
}

// ---------------------------------------------------------------------------
extern "C" void kernel_launch(void* const* d_in, const int* in_sizes, int n_in,
                              void* d_out, int out_size) {
    (void)in_sizes; (void)n_in; (void)out_size;
    const float* x  = (const float*)d_in[0];
    const float* Wg = (const float*)d_in[1];
    const float* W1 = (const float*)d_in[2];
    const float* W3 = (const float*)d_in[3];
    const float* W2 = (const float*)d_in[4];
    float* out = (float*)d_out;

    k_init<<<(EE * CAP + 255) / 256, 256>>>();
    k_gate<<<TT / 8, 256>>>(x, Wg, out);
    k_route<<<TT / 256, 256>>>();
    dim3 g1(CAP / 64, HH / 64, EE);
    k_gemm1<<<g1, 128>>>(x, W1, W3);
    dim3 g2(CAP / 64, DD / 64, EE);
    k_gemm2<<<g2, 128>>>(W2, out);
}

// round 5
// speedup vs baseline: 1.9007x; 1.9007x over previous
#include <cuda_runtime.h>
#include <cuda_bf16.h>
#include <cstdint>

// Problem dims
#define DD 2048
#define HH 1408
#define EE 8
#define TT 4096
#define CAP 4096

#define BK 32
#define NS1 (DD / BK)   // 64
#define NS2 (HH / BK)   // 44
#define AST 36                    // SMEM row stride in words (144B, 16B-aligned, conflict-free frags)
#define OFF_B_W (128 * AST)       // word offset of B region within a stage
#define STAGE_W (256 * AST)       // words per stage (A 128 rows + B 128 rows)
#define STAGE_B (STAGE_W * 4)     // 36864 bytes
#define SMEM_DYN (512 + 3 * STAGE_B)  // srow + 3 stages = 111104

// ---- global scratch (no allocs allowed) ----
__device__ int   g_count[EE];
__device__ int   g_tokens[EE * CAP];
__device__ float g_w[EE * CAP];
__device__ int   g_tidx[TT * 2];
__device__ float g_tw[TT * 2];
__device__ float g_G[(size_t)EE * CAP * HH];   // SwiGLU activations, fp32

// ---------------------------------------------------------------------------
__device__ __forceinline__ uint32_t smem_u32(const void* p) {
    uint32_t a;
    asm("{ .reg .u64 t; cvta.to.shared.u64 t, %1; cvt.u32.u64 %0, t; }" : "=r"(a) : "l"(p));
    return a;
}
#define CP16(dst, src) \
    asm volatile("cp.async.cg.shared.global [%0], [%1], 16;" :: "r"(dst), "l"(src) : "memory")
#define CP_COMMIT() asm volatile("cp.async.commit_group;" ::: "memory")
#define CP_WAIT1()  asm volatile("cp.async.wait_group 1;" ::: "memory")

// warp-level tf32 mma m16n8k8, fp32 accumulate (fragment layouts verified in R2)
__device__ __forceinline__ void mma_tf32(float* c, const uint32_t* a,
                                         uint32_t b0, uint32_t b1) {
    asm volatile(
        "mma.sync.aligned.m16n8k8.row.col.f32.tf32.tf32.f32 "
        "{%0,%1,%2,%3},{%4,%5,%6,%7},{%8,%9},{%0,%1,%2,%3};"
        : "+f"(c[0]), "+f"(c[1]), "+f"(c[2]), "+f"(c[3])
        : "r"(a[0]), "r"(a[1]), "r"(a[2]), "r"(a[3]), "r"(b0), "r"(b1));
}
__device__ __forceinline__ float silu_f(float v) { return v / (1.0f + expf(-v)); }

// ---------------------------------------------------------------------------
__global__ void k_init() {
    int i = blockIdx.x * blockDim.x + threadIdx.x;
    if (i < EE * CAP) { g_tokens[i] = 0; g_w[i] = 0.0f; }
    if (i < EE) g_count[i] = 0;
}

__global__ void k_gate(const float* __restrict__ x,
                       const float* __restrict__ Wg,
                       float* __restrict__ out) {
    int warp = threadIdx.x >> 5, lane = threadIdx.x & 31;
    int t = blockIdx.x * 8 + warp;
    float a[EE];
#pragma unroll
    for (int e = 0; e < EE; e++) a[e] = 0.0f;
    const float* xr = x + (size_t)t * DD;
    float* orow = out + (size_t)t * DD;
    for (int k = lane; k < DD; k += 32) {
        float xv = xr[k];
        orow[k] = xv;
#pragma unroll
        for (int e = 0; e < EE; e++) a[e] += xv * Wg[e * DD + k];
    }
#pragma unroll
    for (int off = 16; off; off >>= 1) {
#pragma unroll
        for (int e = 0; e < EE; e++) a[e] += __shfl_xor_sync(0xffffffffu, a[e], off);
    }
    if (lane == 0) {
        float m = a[0];
#pragma unroll
        for (int e = 1; e < EE; e++) m = fmaxf(m, a[e]);
        float s = 0.0f;
#pragma unroll
        for (int e = 0; e < EE; e++) s += expf(a[e] - m);
        int i1 = 0;
#pragma unroll
        for (int e = 1; e < EE; e++) if (a[e] > a[i1]) i1 = e;
        int i2 = (i1 == 0) ? 1 : 0;
#pragma unroll
        for (int e = 0; e < EE; e++) if (e != i1 && a[e] > a[i2]) i2 = e;
        g_tidx[t * 2 + 0] = i1; g_tw[t * 2 + 0] = expf(a[i1] - m) / s;
        g_tidx[t * 2 + 1] = i2; g_tw[t * 2 + 1] = expf(a[i2] - m) / s;
    }
}

__global__ void k_route() {
    int t = blockIdx.x * blockDim.x + threadIdx.x;
    if (t >= TT) return;
#pragma unroll
    for (int k = 0; k < 2; k++) {
        int e = g_tidx[t * 2 + k];
        int pos = atomicAdd(&g_count[e], 1);
        g_tokens[e * CAP + pos] = t;
        g_w[e * CAP + pos] = g_tw[t * 2 + k];
    }
}

// ---------------------------------------------------------------------------
// gemm1: block 128(M gathered rows) x 128(N = 64 W1 cols | 64 W3 cols), BK=32.
// 4 warps, warp tile 32x128. cp.async 3-stage pipeline, raw-fp32-as-tf32 MMA.
// Epilogue: G = silu(P1)*P3 -> g_G fp32 (64 H-cols per block).
// ---------------------------------------------------------------------------
__global__ void __launch_bounds__(128, 1) k_gemm1(const float* __restrict__ x,
                                                  const float* __restrict__ W1,
                                                  const float* __restrict__ W3) {
    int e = blockIdx.z;
    int cnt = g_count[e];
    int m0 = blockIdx.x * 128;
    if (m0 >= cnt) return;
    int n0 = blockIdx.y * 64;

    extern __shared__ __align__(16) char smem[];
    int* srow = (int*)smem;
    float* stages = (float*)(smem + 512);
    uint32_t sb = smem_u32(smem);
    int tid = threadIdx.x, w = tid >> 5, lane = tid & 31, gr = lane >> 2, tg = lane & 3;

    srow[tid] = g_tokens[e * CAP + m0 + tid] * DD;
    __syncthreads();

    const float* w1b = W1 + ((size_t)e * HH + n0) * DD;
    const float* w3b = W3 + ((size_t)e * HH + n0) * DD;

    auto issue = [&](int s) {
        if (s < NS1) {
            int k0 = s * BK;
            uint32_t bs = sb + 512 + (s % 3) * STAGE_B;
#pragma unroll
            for (int i = 0; i < 8; i++) {
                int u = tid + i * 128, row = u >> 3, c4 = u & 7;
                CP16(bs + (row * AST + c4 * 4) * 4, x + srow[row] + k0 + c4 * 4);
            }
#pragma unroll
            for (int i = 0; i < 8; i++) {
                int u = tid + i * 128, row = u >> 3, c4 = u & 7;
                const float* src = (row < 64) ? (w1b + (size_t)row * DD)
                                              : (w3b + (size_t)(row - 64) * DD);
                CP16(bs + (OFF_B_W + row * AST + c4 * 4) * 4, src + k0 + c4 * 4);
            }
        }
        CP_COMMIT();
    };

    float acc[2][16][4];
#pragma unroll
    for (int mi = 0; mi < 2; mi++)
#pragma unroll
        for (int ni = 0; ni < 16; ni++)
#pragma unroll
            for (int q = 0; q < 4; q++) acc[mi][ni][q] = 0.0f;

    issue(0);
    issue(1);
    for (int s = 0; s < NS1; s++) {
        CP_WAIT1();
        __syncthreads();
        issue(s + 2);
        const float* st = stages + (s % 3) * STAGE_W;
        const float* sB = st + OFF_B_W;
#pragma unroll
        for (int ks = 0; ks < 32; ks += 8) {
            uint32_t a[2][4];
#pragma unroll
            for (int mi = 0; mi < 2; mi++) {
                int r0 = w * 32 + mi * 16 + gr;
                a[mi][0] = *(const uint32_t*)&st[r0 * AST + ks + tg];
                a[mi][1] = *(const uint32_t*)&st[(r0 + 8) * AST + ks + tg];
                a[mi][2] = *(const uint32_t*)&st[r0 * AST + ks + tg + 4];
                a[mi][3] = *(const uint32_t*)&st[(r0 + 8) * AST + ks + tg + 4];
            }
#pragma unroll
            for (int ni = 0; ni < 16; ni++) {
                int n = ni * 8 + gr;
                uint32_t b0 = *(const uint32_t*)&sB[n * AST + ks + tg];
                uint32_t b1 = *(const uint32_t*)&sB[n * AST + ks + tg + 4];
                mma_tf32(acc[0][ni], a[0], b0, b1);
                mma_tf32(acc[1][ni], a[1], b0, b1);
            }
        }
    }

    // epilogue: silu pairing is warp-local (ni vs ni+8)
#pragma unroll
    for (int mi = 0; mi < 2; mi++) {
        int r = m0 + w * 32 + mi * 16 + gr;
        float* gp = g_G + ((size_t)e * CAP + r) * HH + n0;
#pragma unroll
        for (int ni = 0; ni < 8; ni++) {
            int c = ni * 8 + tg * 2;
            float2 v0, v1;
            v0.x = silu_f(acc[mi][ni][0]) * acc[mi][ni + 8][0];
            v0.y = silu_f(acc[mi][ni][1]) * acc[mi][ni + 8][1];
            v1.x = silu_f(acc[mi][ni][2]) * acc[mi][ni + 8][2];
            v1.y = silu_f(acc[mi][ni][3]) * acc[mi][ni + 8][3];
            *(float2*)(gp + c) = v0;
            *(float2*)(gp + (size_t)8 * HH + c) = v1;
        }
    }
}

// ---------------------------------------------------------------------------
// gemm2: block 128(M) x 128(N d-cols), K over H. Same pipeline. Weighted
// atomic scatter-add into out (pre-initialized to residual x).
// ---------------------------------------------------------------------------
__global__ void __launch_bounds__(128, 1) k_gemm2(const float* __restrict__ W2,
                                                  float* __restrict__ out) {
    int e = blockIdx.z;
    int cnt = g_count[e];
    int m0 = blockIdx.x * 128;
    if (m0 >= cnt) return;
    int n0 = blockIdx.y * 128;

    extern __shared__ __align__(16) char smem[];
    float* stages = (float*)(smem + 512);
    uint32_t sb = smem_u32(smem);
    int tid = threadIdx.x, w = tid >> 5, lane = tid & 31, gr = lane >> 2, tg = lane & 3;

    const float* ab  = g_G + ((size_t)e * CAP + m0) * HH;
    const float* w2b = W2 + ((size_t)e * DD + n0) * HH;

    auto issue = [&](int s) {
        if (s < NS2) {
            int k0 = s * BK;
            uint32_t bs = sb + 512 + (s % 3) * STAGE_B;
#pragma unroll
            for (int i = 0; i < 8; i++) {
                int u = tid + i * 128, row = u >> 3, c4 = u & 7;
                CP16(bs + (row * AST + c4 * 4) * 4, ab + (size_t)row * HH + k0 + c4 * 4);
            }
#pragma unroll
            for (int i = 0; i < 8; i++) {
                int u = tid + i * 128, row = u >> 3, c4 = u & 7;
                CP16(bs + (OFF_B_W + row * AST + c4 * 4) * 4, w2b + (size_t)row * HH + k0 + c4 * 4);
            }
        }
        CP_COMMIT();
    };

    float acc[2][16][4];
#pragma unroll
    for (int mi = 0; mi < 2; mi++)
#pragma unroll
        for (int ni = 0; ni < 16; ni++)
#pragma unroll
            for (int q = 0; q < 4; q++) acc[mi][ni][q] = 0.0f;

    issue(0);
    issue(1);
    for (int s = 0; s < NS2; s++) {
        CP_WAIT1();
        __syncthreads();
        issue(s + 2);
        const float* st = stages + (s % 3) * STAGE_W;
        const float* sB = st + OFF_B_W;
#pragma unroll
        for (int ks = 0; ks < 32; ks += 8) {
            uint32_t a[2][4];
#pragma unroll
            for (int mi = 0; mi < 2; mi++) {
                int r0 = w * 32 + mi * 16 + gr;
                a[mi][0] = *(const uint32_t*)&st[r0 * AST + ks + tg];
                a[mi][1] = *(const uint32_t*)&st[(r0 + 8) * AST + ks + tg];
                a[mi][2] = *(const uint32_t*)&st[r0 * AST + ks + tg + 4];
                a[mi][3] = *(const uint32_t*)&st[(r0 + 8) * AST + ks + tg + 4];
            }
#pragma unroll
            for (int ni = 0; ni < 16; ni++) {
                int n = ni * 8 + gr;
                uint32_t b0 = *(const uint32_t*)&sB[n * AST + ks + tg];
                uint32_t b1 = *(const uint32_t*)&sB[n * AST + ks + tg + 4];
                mma_tf32(acc[0][ni], a[0], b0, b1);
                mma_tf32(acc[1][ni], a[1], b0, b1);
            }
        }
    }

    // epilogue: weighted scatter-add
#pragma unroll
    for (int mi = 0; mi < 2; mi++) {
        int rl = m0 + w * 32 + mi * 16 + gr;
        int t0 = g_tokens[e * CAP + rl];
        float w0 = g_w[e * CAP + rl];
        int t1 = g_tokens[e * CAP + rl + 8];
        float w1 = g_w[e * CAP + rl + 8];
        float* o0 = out + (size_t)t0 * DD + n0;
        float* o1 = out + (size_t)t1 * DD + n0;
#pragma unroll
        for (int ni = 0; ni < 16; ni++) {
            int c = ni * 8 + tg * 2;
            atomicAdd(o0 + c,     w0 * acc[mi][ni][0]);
            atomicAdd(o0 + c + 1, w0 * acc[mi][ni][1]);
            atomicAdd(o1 + c,     w1 * acc[mi][ni][2]);
            atomicAdd(o1 + c + 1, w1 * acc[mi][ni][3]);
        }
    }
}

// ---------------------------------------------------------------------------
extern "C" void kernel_launch(void* const* d_in, const int* in_sizes, int n_in,
                              void* d_out, int out_size) {
    (void)in_sizes; (void)n_in; (void)out_size;
    const float* x  = (const float*)d_in[0];
    const float* Wg = (const float*)d_in[1];
    const float* W1 = (const float*)d_in[2];
    const float* W3 = (const float*)d_in[3];
    const float* W2 = (const float*)d_in[4];
    float* out = (float*)d_out;

    cudaFuncSetAttribute(k_gemm1, cudaFuncAttributeMaxDynamicSharedMemorySize, SMEM_DYN);
    cudaFuncSetAttribute(k_gemm2, cudaFuncAttributeMaxDynamicSharedMemorySize, SMEM_DYN);

    k_init<<<(EE * CAP + 255) / 256, 256>>>();
    k_gate<<<TT / 8, 256>>>(x, Wg, out);
    k_route<<<TT / 256, 256>>>();
    dim3 g1(CAP / 128, HH / 64, EE);
    k_gemm1<<<g1, 128, SMEM_DYN>>>(x, W1, W3);
    dim3 g2(CAP / 128, DD / 128, EE);
    k_gemm2<<<g2, 128, SMEM_DYN>>>(W2, out);
}